// round 4
// baseline (speedup 1.0000x reference)
#include <cuda_runtime.h>
#include <cuda_fp16.h>

#define NN 100000
#define EE 3200000
#define GG 2048
#define FIN 9
#define HF 64
#define ZC 96            // H + EXTRA
#define EXTRA_F 32
#define BN_EPS 1e-5f
#define NB_SCAN ((NN + 1023) / 1024)   // 98

// ---------------- scratch (device globals; no allocation allowed) -------------
__device__ __align__(16) __half g_u16[NN * HF];  // dis-scaled transformed features (fp16)
__device__ __align__(16) float  g_h[NN * HF];    // layer activations (fp32)
__device__ int   g_indeg[NN];
__device__ int   g_rowptr[NN + 1];
__device__ int   g_cursor[NN];
__device__ int   g_csr[EE];
__device__ float g_dis[NN];
__device__ int   g_bsum[128];
__device__ int   g_carry[128];
__device__ int   g_gstart[GG + 1];
__device__ float g_z[GG * ZC];
__device__ float g_y0[GG * 128];
__device__ float g_y1[GG * 64];
__device__ float g_y2[GG * 32];
__device__ float g_colsum[128];
__device__ float g_colsq[128];
__device__ float g_scale[128];
__device__ float g_shift[128];

// ---------------- init / CSR build -------------------------------------------
__global__ void k_init() {
    int t = blockIdx.x * blockDim.x + threadIdx.x;
    if (t < NN) g_indeg[t] = 0;
    if (t < 128) { g_colsum[t] = 0.f; g_colsq[t] = 0.f; }
}

__global__ void k_hist(const int4* __restrict__ dst4) {
    int e = blockIdx.x * blockDim.x + threadIdx.x;   // EE/4 quads
    if (e < EE / 4) {
        int4 d = dst4[e];
        atomicAdd(&g_indeg[d.x], 1);
        atomicAdd(&g_indeg[d.y], 1);
        atomicAdd(&g_indeg[d.z], 1);
        atomicAdd(&g_indeg[d.w], 1);
    }
}

__global__ void k_dis() {
    int i = blockIdx.x * blockDim.x + threadIdx.x;
    if (i < NN) g_dis[i] = rsqrtf((float)(g_indeg[i] + 1));   // +1 self loop
}

__global__ void k_scan1() {
    __shared__ int s[1024];
    int gid = blockIdx.x * 1024 + threadIdx.x;
    int v = (gid < NN) ? g_indeg[gid] : 0;
    s[threadIdx.x] = v;
    __syncthreads();
    for (int off = 1; off < 1024; off <<= 1) {
        int t = (threadIdx.x >= off) ? s[threadIdx.x - off] : 0;
        __syncthreads();
        s[threadIdx.x] += t;
        __syncthreads();
    }
    if (gid < NN) g_rowptr[gid] = s[threadIdx.x] - v;   // exclusive (partial)
    if (threadIdx.x == 1023) g_bsum[blockIdx.x] = s[1023];
}

__global__ void k_scan2() {
    __shared__ int s[128];
    int t = threadIdx.x;
    int v = (t < NB_SCAN) ? g_bsum[t] : 0;
    s[t] = v;
    __syncthreads();
    for (int off = 1; off < 128; off <<= 1) {
        int u = (t >= off) ? s[t - off] : 0;
        __syncthreads();
        s[t] += u;
        __syncthreads();
    }
    g_carry[t] = s[t] - v;   // exclusive
}

__global__ void k_scan3() {
    int gid = blockIdx.x * blockDim.x + threadIdx.x;
    if (gid < NN) {
        int r = g_rowptr[gid] + g_carry[gid >> 10];
        g_rowptr[gid] = r;
        g_cursor[gid] = r;
    }
    if (gid == 0) g_rowptr[NN] = EE;
}

__global__ void k_scatter(const int4* __restrict__ src4, const int4* __restrict__ dst4) {
    int e = blockIdx.x * blockDim.x + threadIdx.x;   // EE/4 quads
    if (e < EE / 4) {
        int4 d = dst4[e];
        int4 s = src4[e];
        g_csr[atomicAdd(&g_cursor[d.x], 1)] = s.x;
        g_csr[atomicAdd(&g_cursor[d.y], 1)] = s.y;
        g_csr[atomicAdd(&g_cursor[d.z], 1)] = s.z;
        g_csr[atomicAdd(&g_cursor[d.w], 1)] = s.w;
    }
}

// ---------------- graph boundaries (batch is sorted) -------------------------
__global__ void k_bounds(const int* __restrict__ batch) {
    int g = blockIdx.x * blockDim.x + threadIdx.x;
    if (g > GG) return;
    // lower_bound: first i with batch[i] >= g
    int lo = 0, hi = NN;
    while (lo < hi) {
        int mid = (lo + hi) >> 1;
        if (batch[mid] < g) lo = mid + 1; else hi = mid;
    }
    g_gstart[g] = lo;
}

// ---------------- GCN: transform (u16 = dis * (in @ W)) ----------------------
template <int K>
__global__ void k_transform(const float* __restrict__ in, const float* __restrict__ W,
                            __half* __restrict__ out) {
    __shared__ float Ws[K * HF];
    __shared__ float hs[4 * K];
    for (int idx = threadIdx.x; idx < K * HF; idx += 256) Ws[idx] = W[idx];
    int c = threadIdx.x & 63;
    int r = threadIdx.x >> 6;        // 0..3 node lanes
    int base = blockIdx.x * 64;      // 64 nodes / block
    __syncthreads();
#pragma unroll 1
    for (int it = 0; it < 16; ++it) {
        int nb = base + it * 4;
        if (threadIdx.x < 4 * K) {
            int row = threadIdx.x / K, col = threadIdx.x - row * K;
            int node = nb + row;
            hs[threadIdx.x] = (node < NN) ? in[node * K + col] : 0.f;
        }
        __syncthreads();
        float acc = 0.f;
#pragma unroll
        for (int k = 0; k < K; ++k) acc = fmaf(hs[r * K + k], Ws[k * HF + c], acc);
        int node = nb + r;
        if (node < NN) out[node * HF + c] = __float2half(g_dis[node] * acc);
        __syncthreads();
    }
}

// ---------------- GCN: aggregate (warp per node, fp16 gather, unroll 8) ------
__global__ void __launch_bounds__(256) k_aggregate(const float* __restrict__ bias) {
    int t = blockIdx.x * blockDim.x + threadIdx.x;
    int i = t >> 5;
    int lane = t & 31;
    if (i >= NN) return;
    const __half2* __restrict__ u2 = (const __half2*)g_u16;
    float2 acc = __half22float2(u2[i * 32 + lane]);   // self-loop (u pre-scaled by dis)
    int j = g_rowptr[i], end = g_rowptr[i + 1];
    for (; j + 8 <= end; j += 8) {
        int s0 = g_csr[j],     s1 = g_csr[j + 1], s2 = g_csr[j + 2], s3 = g_csr[j + 3];
        int s4 = g_csr[j + 4], s5 = g_csr[j + 5], s6 = g_csr[j + 6], s7 = g_csr[j + 7];
        float2 a = __half22float2(u2[s0 * 32 + lane]);
        float2 b = __half22float2(u2[s1 * 32 + lane]);
        float2 c = __half22float2(u2[s2 * 32 + lane]);
        float2 d = __half22float2(u2[s3 * 32 + lane]);
        float2 e = __half22float2(u2[s4 * 32 + lane]);
        float2 f = __half22float2(u2[s5 * 32 + lane]);
        float2 g = __half22float2(u2[s6 * 32 + lane]);
        float2 h = __half22float2(u2[s7 * 32 + lane]);
        acc.x += ((a.x + b.x) + (c.x + d.x)) + ((e.x + f.x) + (g.x + h.x));
        acc.y += ((a.y + b.y) + (c.y + d.y)) + ((e.y + f.y) + (g.y + h.y));
    }
    for (; j < end; ++j) {
        float2 a = __half22float2(u2[g_csr[j] * 32 + lane]);
        acc.x += a.x; acc.y += a.y;
    }
    float di = g_dis[i];
    float ox = fmaxf(fmaf(di, acc.x, bias[2 * lane]), 0.f);
    float oy = fmaxf(fmaf(di, acc.y, bias[2 * lane + 1]), 0.f);
    ((float2*)g_h)[i * 32 + lane] = make_float2(ox, oy);
}

// ---------------- global mean pool (contiguous ranges, no atomics) -----------
__global__ void __launch_bounds__(64) k_pool(const float* __restrict__ extra) {
    int g = blockIdx.x;
    int c = threadIdx.x;        // column 0..63
    int s = g_gstart[g], e = g_gstart[g + 1];
    float sum = 0.f;
    for (int i = s; i < e; ++i) sum += g_h[i * HF + c];
    float inv = 1.f / fmaxf((float)(e - s), 1.f);
    g_z[g * ZC + c] = sum * inv;
    if (c < EXTRA_F) g_z[g * ZC + HF + c] = extra[g * EXTRA_F + c];
}

// ---------------- MLP + BatchNorm (BN of previous layer fused into read) -----
template <int K, int C, bool BN_IN>
__global__ void __launch_bounds__(256) k_mlp(const float* __restrict__ z,
                                             const float* __restrict__ W,
                                             const float* __restrict__ b,
                                             float* __restrict__ y) {
    constexpr int RPT = 256 / C;
    __shared__ float Ws[K * C];
    __shared__ float sc[K], sh[K];
    for (int idx = threadIdx.x; idx < K * C; idx += 256) Ws[idx] = W[idx];
    if (BN_IN && threadIdx.x < K) {
        sc[threadIdx.x] = g_scale[threadIdx.x];
        sh[threadIdx.x] = g_shift[threadIdx.x];
    }
    __syncthreads();
    int c = threadIdx.x % C;
    int r0 = threadIdx.x / C;
    const int rowsPerBlock = GG / 16;
    int rbase = blockIdx.x * rowsPerBlock;
    float bc = b[c];
    float s1 = 0.f, s2 = 0.f;
    for (int rr = r0; rr < rowsPerBlock; rr += RPT) {
        int row = rbase + rr;
        const float* __restrict__ zr = z + row * K;
        float acc = bc;
#pragma unroll
        for (int k = 0; k < K; ++k) {
            float v = zr[k];
            if (BN_IN) v = fmaxf(fmaf(v, sc[k], sh[k]), 0.f);
            acc = fmaf(v, Ws[k * C + c], acc);
        }
        y[row * C + c] = acc;
        s1 += acc;
        s2 = fmaf(acc, acc, s2);
    }
    atomicAdd(&g_colsum[c], s1);
    atomicAdd(&g_colsq[c], s2);
}

template <int C>
__global__ void k_bnfin(const float* __restrict__ gam, const float* __restrict__ bet) {
    int c = threadIdx.x;
    if (c >= C) return;
    float mu = g_colsum[c] * (1.f / (float)GG);
    float var = g_colsq[c] * (1.f / (float)GG) - mu * mu;
    float s = gam[c] * rsqrtf(var + BN_EPS);
    g_scale[c] = s;
    g_shift[c] = bet[c] - mu * s;
    g_colsum[c] = 0.f;    // reset for next layer's atomics
    g_colsq[c] = 0.f;
}

__global__ void k_final(const float* __restrict__ W, const float* __restrict__ b,
                        float* __restrict__ out) {
    int t = blockIdx.x * blockDim.x + threadIdx.x;
    int g = t >> 5;
    int lane = t & 31;
    if (g >= GG) return;
    float v = fmaxf(fmaf(g_y2[g * 32 + lane], g_scale[lane], g_shift[lane]), 0.f) * W[lane];
#pragma unroll
    for (int o = 16; o; o >>= 1) v += __shfl_xor_sync(0xFFFFFFFFu, v, o);
    if (lane == 0) out[g] = v + b[0];
}

// ---------------- launch -----------------------------------------------------
extern "C" void kernel_launch(void* const* d_in, const int* in_sizes, int n_in,
                              void* d_out, int out_size) {
    const float* x     = (const float*)d_in[0];
    const int*   ei    = (const int*)d_in[1];
    const int*   batch = (const int*)d_in[2];
    const float* extra = (const float*)d_in[3];
    const float* W1 = (const float*)d_in[4];  const float* b1 = (const float*)d_in[5];
    const float* W2 = (const float*)d_in[6];  const float* b2 = (const float*)d_in[7];
    const float* W3 = (const float*)d_in[8];  const float* b3 = (const float*)d_in[9];
    const float* Wm0 = (const float*)d_in[10]; const float* bm0 = (const float*)d_in[11];
    const float* g0  = (const float*)d_in[12]; const float* be0 = (const float*)d_in[13];
    const float* Wm1 = (const float*)d_in[14]; const float* bm1 = (const float*)d_in[15];
    const float* g1  = (const float*)d_in[16]; const float* be1 = (const float*)d_in[17];
    const float* Wm2 = (const float*)d_in[18]; const float* bm2 = (const float*)d_in[19];
    const float* g2  = (const float*)d_in[20]; const float* be2 = (const float*)d_in[21];
    const float* Wm3 = (const float*)d_in[22]; const float* bm3 = (const float*)d_in[23];
    float* out = (float*)d_out;

    const int* src = ei;
    const int* dst = ei + EE;

    __half* p_u;  float *p_h, *p_y0, *p_y1, *p_y2, *p_z;
    cudaGetSymbolAddress((void**)&p_u, g_u16);
    cudaGetSymbolAddress((void**)&p_h, g_h);
    cudaGetSymbolAddress((void**)&p_y0, g_y0);
    cudaGetSymbolAddress((void**)&p_y1, g_y1);
    cudaGetSymbolAddress((void**)&p_y2, g_y2);
    cudaGetSymbolAddress((void**)&p_z, g_z);

    const int TB = 256;
    // init + CSR build
    k_init<<<(NN + TB - 1) / TB, TB>>>();
    k_hist<<<(EE / 4 + TB - 1) / TB, TB>>>((const int4*)dst);
    k_dis<<<(NN + TB - 1) / TB, TB>>>();
    k_scan1<<<NB_SCAN, 1024>>>();
    k_scan2<<<1, 128>>>();
    k_scan3<<<(NN + TB - 1) / TB, TB>>>();
    k_scatter<<<(EE / 4 + TB - 1) / TB, TB>>>((const int4*)src, (const int4*)dst);
    k_bounds<<<(GG + 1 + TB - 1) / TB, TB>>>(batch);

    const int TGRID = (NN + 63) / 64;
    const int AGRID = (NN * 32 + TB - 1) / TB;

    // GCN layers
    k_transform<FIN><<<TGRID, TB>>>(x, W1, p_u);
    k_aggregate<<<AGRID, TB>>>(b1);
    k_transform<HF><<<TGRID, TB>>>(p_h, W2, p_u);
    k_aggregate<<<AGRID, TB>>>(b2);
    k_transform<HF><<<TGRID, TB>>>(p_h, W3, p_u);
    k_aggregate<<<AGRID, TB>>>(b3);

    // pool + concat extra (batch sorted -> contiguous ranges)
    k_pool<<<GG, 64>>>(extra);

    // MLP with fused BN-on-input
    k_mlp<96, 128, false><<<16, TB>>>(p_z, Wm0, bm0, p_y0);
    k_bnfin<128><<<1, 128>>>(g0, be0);
    k_mlp<128, 64, true><<<16, TB>>>(p_y0, Wm1, bm1, p_y1);
    k_bnfin<64><<<1, 64>>>(g1, be1);
    k_mlp<64, 32, true><<<16, TB>>>(p_y1, Wm2, bm2, p_y2);
    k_bnfin<32><<<1, 32>>>(g2, be2);
    k_final<<<(GG * 32 + TB - 1) / TB, TB>>>(Wm3, bm3, out);
}

// round 9
// speedup vs baseline: 1.2893x; 1.2893x over previous
#include <cuda_runtime.h>
#include <cuda_fp16.h>

#define NN 100000
#define EE 3200000
#define GG 2048
#define FIN 9
#define HF 64
#define ZC 96
#define EXTRA_F 32
#define BN_EPS 1e-5f
#define NB_SCAN ((NN + 1023) / 1024)   // 98

// ---------------- scratch ----------------------------------------------------
__device__ __align__(16) __half g_u16[NN * HF];  // dis-scaled activations (fp16, gather operand)
__device__ __align__(16) float  g_h[NN * HF];    // final layer activations (fp32)
__device__ __align__(16) float  g_s[NN * HF];    // aggregated sums (pre-transform)
__device__ __align__(16) float  g_xs[NN * FIN];  // dis-scaled input features
__device__ __align__(16) float  g_s1[NN * FIN];  // layer-1 aggregate
__device__ int   g_indeg[NN];
__device__ int   g_rowptr[NN + 1];
__device__ int   g_cursor[NN];
__device__ int   g_csr[EE];
__device__ float g_dis[NN];
__device__ int   g_bsum[128];
__device__ int   g_carry[128];
__device__ int   g_gstart[GG + 1];
__device__ float g_z[GG * ZC];
__device__ float g_y0[GG * 128];
__device__ float g_y1[GG * 64];
__device__ float g_y2[GG * 32];
__device__ float g_colsum[128];
__device__ float g_colsq[128];
__device__ float g_scale[128];
__device__ float g_shift[128];

// ---------------- init / CSR build -------------------------------------------
__global__ void k_init() {
    int t = blockIdx.x * blockDim.x + threadIdx.x;
    if (t < NN) g_indeg[t] = 0;
    if (t < 128) { g_colsum[t] = 0.f; g_colsq[t] = 0.f; }
}

__global__ void k_hist(const int4* __restrict__ dst4) {
    int e = blockIdx.x * blockDim.x + threadIdx.x;
    if (e < EE / 4) {
        int4 d = dst4[e];
        atomicAdd(&g_indeg[d.x], 1);
        atomicAdd(&g_indeg[d.y], 1);
        atomicAdd(&g_indeg[d.z], 1);
        atomicAdd(&g_indeg[d.w], 1);
    }
}

__global__ void k_scan1() {       // also computes dis
    __shared__ int s[1024];
    int gid = blockIdx.x * 1024 + threadIdx.x;
    int v = (gid < NN) ? g_indeg[gid] : 0;
    if (gid < NN) g_dis[gid] = rsqrtf((float)(v + 1));
    s[threadIdx.x] = v;
    __syncthreads();
    for (int off = 1; off < 1024; off <<= 1) {
        int t = (threadIdx.x >= off) ? s[threadIdx.x - off] : 0;
        __syncthreads();
        s[threadIdx.x] += t;
        __syncthreads();
    }
    if (gid < NN) g_rowptr[gid] = s[threadIdx.x] - v;
    if (threadIdx.x == 1023) g_bsum[blockIdx.x] = s[1023];
}

__global__ void k_scan2() {
    __shared__ int s[128];
    int t = threadIdx.x;
    int v = (t < NB_SCAN) ? g_bsum[t] : 0;
    s[t] = v;
    __syncthreads();
    for (int off = 1; off < 128; off <<= 1) {
        int u = (t >= off) ? s[t - off] : 0;
        __syncthreads();
        s[t] += u;
        __syncthreads();
    }
    g_carry[t] = s[t] - v;
}

__global__ void k_scan3() {
    int gid = blockIdx.x * blockDim.x + threadIdx.x;
    if (gid < NN) {
        int r = g_rowptr[gid] + g_carry[gid >> 10];
        g_rowptr[gid] = r;
        g_cursor[gid] = r;
    }
    if (gid == 0) g_rowptr[NN] = EE;
}

__global__ void k_scatter(const int4* __restrict__ src4, const int4* __restrict__ dst4) {
    int e = blockIdx.x * blockDim.x + threadIdx.x;
    if (e < EE / 4) {
        int4 d = dst4[e];
        int4 s = src4[e];
        g_csr[atomicAdd(&g_cursor[d.x], 1)] = s.x;
        g_csr[atomicAdd(&g_cursor[d.y], 1)] = s.y;
        g_csr[atomicAdd(&g_cursor[d.z], 1)] = s.z;
        g_csr[atomicAdd(&g_cursor[d.w], 1)] = s.w;
    }
}

__global__ void k_bounds(const int* __restrict__ batch) {
    int g = blockIdx.x * blockDim.x + threadIdx.x;
    if (g > GG) return;
    int lo = 0, hi = NN;
    while (lo < hi) {
        int mid = (lo + hi) >> 1;
        if (batch[mid] < g) lo = mid + 1; else hi = mid;
    }
    g_gstart[g] = lo;
}

// ---------------- pre-scale x by dis -----------------------------------------
__global__ void k_prescale(const float* __restrict__ x) {
    int t = blockIdx.x * blockDim.x + threadIdx.x;
    if (t < NN * FIN) g_xs[t] = x[t] * g_dis[t / FIN];
}

// ---------------- layer-1 aggregate: s1 = dis * (A_hat * xs), 9-wide ---------
__global__ void __launch_bounds__(256) k_agg1() {
    int t = blockIdx.x * blockDim.x + threadIdx.x;
    int i = t >> 5;
    int lane = t & 31;
    if (i >= NN) return;
    int grp = lane / 9;              // 0..2 usable, 3 idle
    int fl = lane - grp * 9;
    bool gl = (lane < 27);
    float acc = 0.f;
    int j = g_rowptr[i], end = g_rowptr[i + 1];
    for (; j < end; j += 6) {
        int e0 = j + grp, e1 = j + 3 + grp;
        int s0 = (gl && e0 < end) ? g_csr[e0] : -1;
        int s1 = (gl && e1 < end) ? g_csr[e1] : -1;
        float v0 = (s0 >= 0) ? g_xs[s0 * FIN + fl] : 0.f;
        float v1 = (s1 >= 0) ? g_xs[s1 * FIN + fl] : 0.f;
        acc += v0 + v1;
    }
    float a1 = __shfl_down_sync(0xFFFFFFFFu, acc, 9);
    float a2 = __shfl_down_sync(0xFFFFFFFFu, acc, 18);
    acc += a1 + a2;
    if (lane < 9) {
        acc += g_xs[i * FIN + lane];                 // self loop
        g_s1[i * FIN + lane] = g_dis[i] * acc;
    }
}

// ---------------- layer 2/3 aggregate: s = dis * (A_hat * u16), 64-wide ------
__global__ void __launch_bounds__(256) k_agg64() {
    int t = blockIdx.x * blockDim.x + threadIdx.x;
    int i = t >> 5;
    int lane = t & 31;
    if (i >= NN) return;
    const __half2* __restrict__ u2 = (const __half2*)g_u16;
    float2 acc = __half22float2(u2[i * 32 + lane]);     // self loop
    int j = g_rowptr[i], end = g_rowptr[i + 1];
    for (; j + 8 <= end; j += 8) {
        int s0 = g_csr[j],     s1 = g_csr[j + 1], s2 = g_csr[j + 2], s3 = g_csr[j + 3];
        int s4 = g_csr[j + 4], s5 = g_csr[j + 5], s6 = g_csr[j + 6], s7 = g_csr[j + 7];
        float2 a = __half22float2(u2[s0 * 32 + lane]);
        float2 b = __half22float2(u2[s1 * 32 + lane]);
        float2 c = __half22float2(u2[s2 * 32 + lane]);
        float2 d = __half22float2(u2[s3 * 32 + lane]);
        float2 e = __half22float2(u2[s4 * 32 + lane]);
        float2 f = __half22float2(u2[s5 * 32 + lane]);
        float2 g = __half22float2(u2[s6 * 32 + lane]);
        float2 h = __half22float2(u2[s7 * 32 + lane]);
        acc.x += ((a.x + b.x) + (c.x + d.x)) + ((e.x + f.x) + (g.x + h.x));
        acc.y += ((a.y + b.y) + (c.y + d.y)) + ((e.y + f.y) + (g.y + h.y));
    }
    for (; j < end; ++j) {
        float2 a = __half22float2(u2[g_csr[j] * 32 + lane]);
        acc.x += a.x; acc.y += a.y;
    }
    float d = g_dis[i];
    ((float2*)g_s)[i * 32 + lane] = make_float2(d * acc.x, d * acc.y);
}

// ---------------- transform K=9: u16 = dis * relu(s1 @ W1 + b1) --------------
__global__ void __launch_bounds__(256) k_t9(const float* __restrict__ W,
                                            const float* __restrict__ b) {
    __shared__ float Ws[FIN * 64];
    __shared__ float inT[FIN * 64];   // [k][node]
    int t = threadIdx.x;
    int base = blockIdx.x * 64;
    for (int idx = t; idx < FIN * 64; idx += 256) Ws[idx] = W[idx];
    for (int idx = t; idx < FIN * 64; idx += 256) {
        int node = idx / FIN, k = idx - node * FIN;
        int gn = base + node;
        inT[k * 64 + node] = (gn < NN) ? g_s1[gn * FIN + k] : 0.f;
    }
    __syncthreads();
    int tc = t & 15, tr = t >> 4;
    float acc[4][4] = {};
#pragma unroll
    for (int k = 0; k < FIN; ++k) {
        float4 wv = *(const float4*)&Ws[k * 64 + tc * 4];
        float4 av = *(const float4*)&inT[k * 64 + tr * 4];
        acc[0][0] = fmaf(av.x, wv.x, acc[0][0]); acc[0][1] = fmaf(av.x, wv.y, acc[0][1]);
        acc[0][2] = fmaf(av.x, wv.z, acc[0][2]); acc[0][3] = fmaf(av.x, wv.w, acc[0][3]);
        acc[1][0] = fmaf(av.y, wv.x, acc[1][0]); acc[1][1] = fmaf(av.y, wv.y, acc[1][1]);
        acc[1][2] = fmaf(av.y, wv.z, acc[1][2]); acc[1][3] = fmaf(av.y, wv.w, acc[1][3]);
        acc[2][0] = fmaf(av.z, wv.x, acc[2][0]); acc[2][1] = fmaf(av.z, wv.y, acc[2][1]);
        acc[2][2] = fmaf(av.z, wv.z, acc[2][2]); acc[2][3] = fmaf(av.z, wv.w, acc[2][3]);
        acc[3][0] = fmaf(av.w, wv.x, acc[3][0]); acc[3][1] = fmaf(av.w, wv.y, acc[3][1]);
        acc[3][2] = fmaf(av.w, wv.z, acc[3][2]); acc[3][3] = fmaf(av.w, wv.w, acc[3][3]);
    }
    float4 bv = *(const float4*)&b[tc * 4];
#pragma unroll
    for (int i = 0; i < 4; ++i) {
        int node = base + tr * 4 + i;
        if (node >= NN) break;
        float d = g_dis[node];
        float v0 = fmaxf(acc[i][0] + bv.x, 0.f) * d;
        float v1 = fmaxf(acc[i][1] + bv.y, 0.f) * d;
        float v2 = fmaxf(acc[i][2] + bv.z, 0.f) * d;
        float v3 = fmaxf(acc[i][3] + bv.w, 0.f) * d;
        __half2* o = (__half2*)&g_u16[node * 64 + tc * 4];
        o[0] = __floats2half2_rn(v0, v1);
        o[1] = __floats2half2_rn(v2, v3);
    }
}

// ---------------- transform K=64 (register-tiled GEMM) -----------------------
template <bool HALF_OUT>
__global__ void __launch_bounds__(256) k_t64(const float* __restrict__ W,
                                             const float* __restrict__ b) {
    __shared__ float Ws[64 * 64];
    __shared__ float inT[64 * 64];   // [k][node]
    int t = threadIdx.x;
    int base = blockIdx.x * 64;
    for (int idx = t * 4; idx < 4096; idx += 1024)
        *(float4*)&Ws[idx] = *(const float4*)&W[idx];
    {
        int node = t & 63, kb = t >> 6;       // kb 0..3, k range kb*16..+16
        int gn = base + node;
        int cn = (gn < NN) ? gn : (NN - 1);
        const float4* srow = (const float4*)&g_s[cn * 64];
#pragma unroll
        for (int q = 0; q < 4; ++q) {
            float4 v = srow[kb * 4 + q];
            int k0 = kb * 16 + q * 4;
            inT[(k0 + 0) * 64 + node] = v.x;
            inT[(k0 + 1) * 64 + node] = v.y;
            inT[(k0 + 2) * 64 + node] = v.z;
            inT[(k0 + 3) * 64 + node] = v.w;
        }
    }
    __syncthreads();
    int tc = t & 15, tr = t >> 4;
    float acc[4][4] = {};
#pragma unroll 8
    for (int k = 0; k < 64; ++k) {
        float4 wv = *(const float4*)&Ws[k * 64 + tc * 4];
        float4 av = *(const float4*)&inT[k * 64 + tr * 4];
        acc[0][0] = fmaf(av.x, wv.x, acc[0][0]); acc[0][1] = fmaf(av.x, wv.y, acc[0][1]);
        acc[0][2] = fmaf(av.x, wv.z, acc[0][2]); acc[0][3] = fmaf(av.x, wv.w, acc[0][3]);
        acc[1][0] = fmaf(av.y, wv.x, acc[1][0]); acc[1][1] = fmaf(av.y, wv.y, acc[1][1]);
        acc[1][2] = fmaf(av.y, wv.z, acc[1][2]); acc[1][3] = fmaf(av.y, wv.w, acc[1][3]);
        acc[2][0] = fmaf(av.z, wv.x, acc[2][0]); acc[2][1] = fmaf(av.z, wv.y, acc[2][1]);
        acc[2][2] = fmaf(av.z, wv.z, acc[2][2]); acc[2][3] = fmaf(av.z, wv.w, acc[2][3]);
        acc[3][0] = fmaf(av.w, wv.x, acc[3][0]); acc[3][1] = fmaf(av.w, wv.y, acc[3][1]);
        acc[3][2] = fmaf(av.w, wv.z, acc[3][2]); acc[3][3] = fmaf(av.w, wv.w, acc[3][3]);
    }
    float4 bv = *(const float4*)&b[tc * 4];
#pragma unroll
    for (int i = 0; i < 4; ++i) {
        int node = base + tr * 4 + i;
        if (node >= NN) break;
        float v0 = fmaxf(acc[i][0] + bv.x, 0.f);
        float v1 = fmaxf(acc[i][1] + bv.y, 0.f);
        float v2 = fmaxf(acc[i][2] + bv.z, 0.f);
        float v3 = fmaxf(acc[i][3] + bv.w, 0.f);
        if (HALF_OUT) {
            float d = g_dis[node];
            __half2* o = (__half2*)&g_u16[node * 64 + tc * 4];
            o[0] = __floats2half2_rn(v0 * d, v1 * d);
            o[1] = __floats2half2_rn(v2 * d, v3 * d);
        } else {
            *(float4*)&g_h[node * 64 + tc * 4] = make_float4(v0, v1, v2, v3);
        }
    }
}

// ---------------- global mean pool -------------------------------------------
__global__ void __launch_bounds__(64) k_pool(const float* __restrict__ extra) {
    int g = blockIdx.x;
    int c = threadIdx.x;
    int s = g_gstart[g], e = g_gstart[g + 1];
    float sum = 0.f;
    for (int i = s; i < e; ++i) sum += g_h[i * HF + c];
    float inv = 1.f / fmaxf((float)(e - s), 1.f);
    g_z[g * ZC + c] = sum * inv;
    if (c < EXTRA_F) g_z[g * ZC + HF + c] = extra[g * EXTRA_F + c];
}

// ---------------- MLP + BatchNorm --------------------------------------------
template <int K, int C, bool BN_IN>
__global__ void __launch_bounds__(256) k_mlp(const float* __restrict__ z,
                                             const float* __restrict__ W,
                                             const float* __restrict__ b,
                                             float* __restrict__ y) {
    constexpr int RPT = 256 / C;
    __shared__ float Ws[K * C];
    __shared__ float sc[K], sh[K];
    for (int idx = threadIdx.x; idx < K * C; idx += 256) Ws[idx] = W[idx];
    if (BN_IN && threadIdx.x < K) {
        sc[threadIdx.x] = g_scale[threadIdx.x];
        sh[threadIdx.x] = g_shift[threadIdx.x];
    }
    __syncthreads();
    int c = threadIdx.x % C;
    int r0 = threadIdx.x / C;
    const int rowsPerBlock = GG / 16;
    int rbase = blockIdx.x * rowsPerBlock;
    float bc = b[c];
    float s1 = 0.f, s2 = 0.f;
    for (int rr = r0; rr < rowsPerBlock; rr += RPT) {
        int row = rbase + rr;
        const float* __restrict__ zr = z + row * K;
        float acc = bc;
#pragma unroll
        for (int k = 0; k < K; ++k) {
            float v = zr[k];
            if (BN_IN) v = fmaxf(fmaf(v, sc[k], sh[k]), 0.f);
            acc = fmaf(v, Ws[k * C + c], acc);
        }
        y[row * C + c] = acc;
        s1 += acc;
        s2 = fmaf(acc, acc, s2);
    }
    atomicAdd(&g_colsum[c], s1);
    atomicAdd(&g_colsq[c], s2);
}

template <int C>
__global__ void k_bnfin(const float* __restrict__ gam, const float* __restrict__ bet) {
    int c = threadIdx.x;
    if (c >= C) return;
    float mu = g_colsum[c] * (1.f / (float)GG);
    float var = g_colsq[c] * (1.f / (float)GG) - mu * mu;
    float s = gam[c] * rsqrtf(var + BN_EPS);
    g_scale[c] = s;
    g_shift[c] = bet[c] - mu * s;
    g_colsum[c] = 0.f;
    g_colsq[c] = 0.f;
}

__global__ void k_final(const float* __restrict__ W, const float* __restrict__ b,
                        float* __restrict__ out) {
    int t = blockIdx.x * blockDim.x + threadIdx.x;
    int g = t >> 5;
    int lane = t & 31;
    if (g >= GG) return;
    float v = fmaxf(fmaf(g_y2[g * 32 + lane], g_scale[lane], g_shift[lane]), 0.f) * W[lane];
#pragma unroll
    for (int o = 16; o; o >>= 1) v += __shfl_xor_sync(0xFFFFFFFFu, v, o);
    if (lane == 0) out[g] = v + b[0];
}

// ---------------- launch -----------------------------------------------------
extern "C" void kernel_launch(void* const* d_in, const int* in_sizes, int n_in,
                              void* d_out, int out_size) {
    const float* x     = (const float*)d_in[0];
    const int*   ei    = (const int*)d_in[1];
    const int*   batch = (const int*)d_in[2];
    const float* extra = (const float*)d_in[3];
    const float* W1 = (const float*)d_in[4];  const float* b1 = (const float*)d_in[5];
    const float* W2 = (const float*)d_in[6];  const float* b2 = (const float*)d_in[7];
    const float* W3 = (const float*)d_in[8];  const float* b3 = (const float*)d_in[9];
    const float* Wm0 = (const float*)d_in[10]; const float* bm0 = (const float*)d_in[11];
    const float* g0  = (const float*)d_in[12]; const float* be0 = (const float*)d_in[13];
    const float* Wm1 = (const float*)d_in[14]; const float* bm1 = (const float*)d_in[15];
    const float* g1  = (const float*)d_in[16]; const float* be1 = (const float*)d_in[17];
    const float* Wm2 = (const float*)d_in[18]; const float* bm2 = (const float*)d_in[19];
    const float* g2  = (const float*)d_in[20]; const float* be2 = (const float*)d_in[21];
    const float* Wm3 = (const float*)d_in[22]; const float* bm3 = (const float*)d_in[23];
    float* out = (float*)d_out;

    const int* src = ei;
    const int* dst = ei + EE;

    float *p_z, *p_y0, *p_y1, *p_y2;
    cudaGetSymbolAddress((void**)&p_z, g_z);
    cudaGetSymbolAddress((void**)&p_y0, g_y0);
    cudaGetSymbolAddress((void**)&p_y1, g_y1);
    cudaGetSymbolAddress((void**)&p_y2, g_y2);

    const int TB = 256;
    // CSR build
    k_init<<<(NN + TB - 1) / TB, TB>>>();
    k_hist<<<(EE / 4 + TB - 1) / TB, TB>>>((const int4*)dst);
    k_scan1<<<NB_SCAN, 1024>>>();
    k_scan2<<<1, 128>>>();
    k_scan3<<<(NN + TB - 1) / TB, TB>>>();
    k_scatter<<<(EE / 4 + TB - 1) / TB, TB>>>((const int4*)src, (const int4*)dst);
    k_bounds<<<(GG + 1 + TB - 1) / TB, TB>>>(batch);
    k_prescale<<<(NN * FIN + TB - 1) / TB, TB>>>(x);

    const int AGRID = (NN * 32 + TB - 1) / TB;
    const int TGRID = (NN + 63) / 64;

    // GCN layers (aggregate-first: relu(A(hW)+b) == relu((Ah)W+b))
    k_agg1<<<AGRID, TB>>>();
    k_t9<<<TGRID, TB>>>(W1, b1);
    k_agg64<<<AGRID, TB>>>();
    k_t64<true><<<TGRID, TB>>>(W2, b2);
    k_agg64<<<AGRID, TB>>>();
    k_t64<false><<<TGRID, TB>>>(W3, b3);

    // pool + MLP
    k_pool<<<GG, 64>>>(extra);
    k_mlp<96, 128, false><<<16, TB>>>(p_z, Wm0, bm0, p_y0);
    k_bnfin<128><<<1, 128>>>(g0, be0);
    k_mlp<128, 64, true><<<16, TB>>>(p_y0, Wm1, bm1, p_y1);
    k_bnfin<64><<<1, 64>>>(g1, be1);
    k_mlp<64, 32, true><<<16, TB>>>(p_y1, Wm2, bm2, p_y2);
    k_bnfin<32><<<1, 32>>>(g2, be2);
    k_final<<<(GG * 32 + TB - 1) / TB, TB>>>(Wm3, bm3, out);
}